// round 11
// baseline (speedup 1.0000x reference)
#include <cuda_runtime.h>
#include <cuda_fp16.h>
#include <mma.h>
#include <math.h>

#define MAXN 100000
#define MAXE 1600000
typedef unsigned long long u64;
using namespace nvcuda;

// ---------------- scratch ----------------
__device__ unsigned g_ft16[MAXN * 48];  // fp16 ft: [0..31]=(h0,h1) pairs/lane, [32..47]=h2 pairs
__device__ float  g_h [MAXN * 96];
__device__ float4 g_el4[MAXN];
__device__ float4 g_er4[MAXN];
__device__ float4 g_eepA[MAXE];      // layer-1 ee terms, edge order
__device__ float4 g_eepB[MAXE];      // layer-2 ee terms, edge order
__device__ float4 g_eec24[MAXE];     // layer-2 ee terms, CSR order
__device__ float4 g_wc4[MAXE];       // exp weights (x0,x1,x2, src-as-bits), CSR order
__device__ int    g_srcc[MAXE];
__device__ int    g_dstc[MAXE];
__device__ int    g_pos [MAXE];
__device__ int    g_deg [MAXN];
__device__ int    g_off [MAXN + 1];
__device__ int    g_woff[MAXN];
__device__ int    g_bsum[128];
__device__ int    g_boff[128];
__device__ float  g_P[MAXN * 10];
__device__ float  g_Q[MAXN * 10];
__device__ float  g_Ve[2][32][3];

__device__ __forceinline__ float leaky(float w) { return (w > 0.f) ? w : 0.2f * w; }

// ---------------- K0: fold We @ ae for both layers ----------------
__global__ void k_ve(const float* __restrict__ We1, const float* __restrict__ ae1,
                     const float* __restrict__ We2, const float* __restrict__ ae2) {
    int t = threadIdx.x;
    if (t >= 192) return;
    int c = t / 96, r = t % 96, d = r / 3, h = r % 3;
    const float* We = c ? We2 : We1;
    const float* ae = c ? ae2 : ae1;
    float s = 0.f;
    #pragma unroll
    for (int f = 0; f < 32; f++) s = fmaf(We[d * 96 + h * 32 + f], ae[h * 32 + f], s);
    g_Ve[c][d][h] = s;
}

// ---------------- node transform: wmma fp16 GEMM (fp32 accum) ----------------------
template <int K>
__global__ void __launch_bounds__(256)
k_wgemm(const float* __restrict__ in,    // nullptr => read g_h
        const float* __restrict__ W,
        const float* __restrict__ al, const float* __restrict__ ar,
        int n) {
    constexpr int AP = K + 8;
    constexpr int ABYTES = 64 * AP * 2;
    constexpr int BBYTES = K * 96 * 2;
    constexpr int OBYTES = 64 * 100 * 4;
    constexpr int SBYTES = (ABYTES + BBYTES > OBYTES) ? (ABYTES + BBYTES) : OBYTES;
    __shared__ __align__(16) char raw[SBYTES];
    __half* sA = (__half*)raw;                   // [64][AP]
    __half* sB = (__half*)(raw + ABYTES);        // [K][96]
    float*  Os = (float*)raw;                    // [64][100] (overlays after compute)
    __shared__ float sal[96], sar[96];

    int tid = threadIdx.x;
    if (tid < 96) { sal[tid] = al[tid]; sar[tid] = ar[tid]; }

    int nb = blockIdx.x * 64;
    const float* base = in ? in : g_h;

    for (int i = tid; i < 64 * (K / 4); i += 256) {
        int row = i / (K / 4), kq = i % (K / 4);
        int gr = nb + row; if (gr >= n) gr = n - 1;
        float4 v = ((const float4*)(base + (size_t)gr * K))[kq];
        __half* d = sA + row * AP + kq * 4;
        d[0] = __float2half(v.x); d[1] = __float2half(v.y);
        d[2] = __float2half(v.z); d[3] = __float2half(v.w);
    }
    for (int i = tid; i < K * 24; i += 256) {
        float4 v = ((const float4*)W)[i];
        __half* d = sB + i * 4;
        d[0] = __float2half(v.x); d[1] = __float2half(v.y);
        d[2] = __float2half(v.z); d[3] = __float2half(v.w);
    }
    __syncthreads();

    int wid = tid >> 5;
    int mt  = wid & 3;
    int ng  = (wid >> 2) * 3;

    wmma::fragment<wmma::accumulator, 16, 16, 16, float> c[3];
    #pragma unroll
    for (int j = 0; j < 3; j++) wmma::fill_fragment(c[j], 0.f);

    #pragma unroll
    for (int kt = 0; kt < K / 16; kt++) {
        wmma::fragment<wmma::matrix_a, 16, 16, 16, __half, wmma::row_major> a;
        wmma::load_matrix_sync(a, sA + mt * 16 * AP + kt * 16, AP);
        #pragma unroll
        for (int j = 0; j < 3; j++) {
            wmma::fragment<wmma::matrix_b, 16, 16, 16, __half, wmma::row_major> b;
            wmma::load_matrix_sync(b, sB + kt * 16 * 96 + (ng + j) * 16, 96);
            wmma::mma_sync(c[j], a, b, c[j]);
        }
    }
    __syncthreads();

    #pragma unroll
    for (int j = 0; j < 3; j++)
        wmma::store_matrix_sync(Os + mt * 16 * 100 + (ng + j) * 16, c[j], 100, wmma::mem_row_major);
    __syncthreads();

    // fp32 h store (needed by wgemm<96> input and k_pq)
    for (int i = tid; i < 64 * 32; i += 256) {
        int nl = i >> 5, j0 = i & 31;
        int node = nb + nl;
        if (node < n) {
            const float* orow = Os + nl * 100;
            // ft16 packed store
            __half2 p01 = __floats2half2_rn(orow[j0], orow[j0 + 32]);
            g_ft16[(size_t)node * 48 + j0] = *(unsigned*)&p01;
            if (j0 < 16) {
                __half2 p2 = __floats2half2_rn(orow[64 + 2 * j0], orow[64 + 2 * j0 + 1]);
                g_ft16[(size_t)node * 48 + 32 + j0] = *(unsigned*)&p2;
            }
        }
    }
    // el/er: 64 threads, one node each
    if (tid < 64 && nb + tid < n) {
        const float4* orow = (const float4*)(Os + tid * 100);
        float el[3] = {0.f, 0.f, 0.f}, er[3] = {0.f, 0.f, 0.f};
        #pragma unroll
        for (int q = 0; q < 24; q++) {
            float4 v = orow[q];
            float xs[4] = {v.x, v.y, v.z, v.w};
            #pragma unroll
            for (int j = 0; j < 4; j++) {
                int cix = q * 4 + j, h = cix >> 5;
                el[h] = fmaf(xs[j], sal[cix], el[h]);
                er[h] = fmaf(xs[j], sar[cix], er[h]);
            }
        }
        g_el4[nb + tid] = make_float4(el[0], el[1], el[2], 0.f);
        g_er4[nb + tid] = make_float4(er[0], er[1], er[2], 0.f);
    }
}

// ---------------- eepre: efeats GEMV only (edge order; needs only Ve) --------------
__global__ void k_eepre(const float* __restrict__ ef, int e_cnt) {
    __shared__ float sVe[192];
    if (threadIdx.x < 192) sVe[threadIdx.x] = ((const float*)g_Ve)[threadIdx.x];
    __syncthreads();
    int e = blockIdx.x * blockDim.x + threadIdx.x;
    if (e >= e_cnt) return;
    const float4* p = (const float4*)(ef + (size_t)e * 32);
    float acc0 = 0, acc1 = 0, acc2 = 0, acc3 = 0, acc4 = 0, acc5 = 0;
    #pragma unroll
    for (int q = 0; q < 8; q++) {
        float4 v = p[q];
        float xs[4] = {v.x, v.y, v.z, v.w};
        #pragma unroll
        for (int j = 0; j < 4; j++) {
            int d = q * 4 + j;
            float x = xs[j];
            acc0 = fmaf(x, sVe[d * 3 + 0],      acc0);
            acc1 = fmaf(x, sVe[d * 3 + 1],      acc1);
            acc2 = fmaf(x, sVe[d * 3 + 2],      acc2);
            acc3 = fmaf(x, sVe[96 + d * 3 + 0], acc3);
            acc4 = fmaf(x, sVe[96 + d * 3 + 1], acc4);
            acc5 = fmaf(x, sVe[96 + d * 3 + 2], acc5);
        }
    }
    g_eepA[e] = make_float4(acc0, acc1, acc2, 0.f);
    g_eepB[e] = make_float4(acc3, acc4, acc5, 0.f);
}

// ---------------- combine: el/er gather + exp, scatter to CSR ----------------------
__global__ void k_combine(const int* __restrict__ src, const int* __restrict__ dst,
                          int e_cnt) {
    int e = blockIdx.x * blockDim.x + threadIdx.x;
    if (e >= e_cnt) return;
    float4 A = g_eepA[e];
    int sn = src[e], dn = dst[e];
    float4 el = g_el4[sn];
    float4 er = g_er4[dn];
    float x0 = __expf(leaky(el.x + er.x + A.x));
    float x1 = __expf(leaky(el.y + er.y + A.y));
    float x2 = __expf(leaky(el.z + er.z + A.z));
    int pp = g_pos[e];
    g_wc4[pp]   = make_float4(x0, x1, x2, __int_as_float(sn));
    g_eec24[pp] = g_eepB[e];
}

// ---------------- layer-2 exp weights: edge-parallel over CSR slots ----------------
__global__ void k_wc2(int e_cnt) {
    int i = blockIdx.x * blockDim.x + threadIdx.x;
    if (i >= e_cnt) return;
    int sn = g_srcc[i], dn = g_dstc[i];
    float4 el = g_el4[sn];
    float4 er = g_er4[dn];
    float4 ee = g_eec24[i];
    float x0 = __expf(leaky(el.x + er.x + ee.x));
    float x1 = __expf(leaky(el.y + er.y + ee.y));
    float x2 = __expf(leaky(el.z + er.z + ee.z));
    g_wc4[i] = make_float4(x0, x1, x2, __int_as_float(sn));
}

// ---------------- CSR build ----------------
__global__ void k_zero_deg(int n) {
    int i = blockIdx.x * blockDim.x + threadIdx.x;
    if (i < n) g_deg[i] = 0;
}
__global__ void k_deg(const int* __restrict__ dst, int e) {
    int i = blockIdx.x * blockDim.x + threadIdx.x;
    if (i < e) atomicAdd(&g_deg[dst[i]], 1);
}
__global__ void k_scan1(int n) {
    __shared__ int s[1024];
    int idx = blockIdx.x * 1024 + threadIdx.x;
    int v = (idx < n) ? g_deg[idx] : 0;
    s[threadIdx.x] = v;
    __syncthreads();
    #pragma unroll
    for (int off = 1; off < 1024; off <<= 1) {
        int t = (threadIdx.x >= off) ? s[threadIdx.x - off] : 0;
        __syncthreads();
        s[threadIdx.x] += t;
        __syncthreads();
    }
    if (idx < n) g_off[idx] = s[threadIdx.x] - v;
    if (threadIdx.x == 1023) g_bsum[blockIdx.x] = s[1023];
}
__global__ void k_scan2(int nb) {
    __shared__ int s[128];
    int tid = threadIdx.x;
    int v = (tid < nb) ? g_bsum[tid] : 0;
    s[tid] = v;
    __syncthreads();
    #pragma unroll
    for (int off = 1; off < 128; off <<= 1) {
        int t = (tid >= off) ? s[tid - off] : 0;
        __syncthreads();
        s[tid] += t;
        __syncthreads();
    }
    if (tid < nb) g_boff[tid] = s[tid] - v;
}
__global__ void k_scan3(int n, int e) {
    int idx = blockIdx.x * 1024 + threadIdx.x;
    if (idx < n) {
        int o = g_off[idx] + g_boff[blockIdx.x];
        g_off[idx] = o;
        g_woff[idx] = o;
    }
    if (idx == 0) g_off[n] = e;
}
__global__ void k_scatter(const int* __restrict__ src, const int* __restrict__ dst, int e) {
    int i = blockIdx.x * blockDim.x + threadIdx.x;
    if (i < e) {
        int d = dst[i];
        int p = atomicAdd(&g_woff[d], 1);
        g_srcc[p] = src[i];
        g_dstc[p] = d;
        g_pos[i] = p;
    }
}

// ---------------- conv: single sweep, fp16 ft gather (2 LDG/edge) ------------------
__global__ void k_conv(const float* __restrict__ bias, int n, int do_relu) {
    int gw   = (blockIdx.x * blockDim.x + threadIdx.x) >> 5;
    int lane = threadIdx.x & 31;
    if (gw >= n) return;
    int beg = g_off[gw], end = g_off[gw + 1];
    float b0 = bias[lane], b1 = bias[lane + 32], b2 = bias[lane + 64];
    float out0, out1, out2;
    if (beg == end) {
        out0 = b0; out1 = b1; out2 = b2;
    } else {
        float s0 = 0.f, s1 = 0.f, s2 = 0.f;
        float a0 = 0.f, a1 = 0.f, a2 = 0.f;
        int half_sel = lane & 1;
        int idx2 = 32 + (lane >> 1);
        #pragma unroll 8
        for (int i = beg; i < end; i++) {
            float4 x = g_wc4[i];                         // uniform LDG.128 (w + src)
            int sn = __float_as_int(x.w);
            const unsigned* fr = g_ft16 + (size_t)sn * 48;
            unsigned a01 = fr[lane];                     // gather 1 (128B/warp)
            unsigned a2v = fr[idx2];                     // gather 2 (64B/warp)
            __half2 h01 = *(__half2*)&a01;
            __half2 h2p = *(__half2*)&a2v;
            float2 f01 = __half22float2(h01);
            float2 f2p = __half22float2(h2p);
            float f2 = half_sel ? f2p.y : f2p.x;
            a0 = fmaf(x.x, f01.x, a0);
            a1 = fmaf(x.y, f01.y, a1);
            a2 = fmaf(x.z, f2,    a2);
            s0 += x.x; s1 += x.y; s2 += x.z;
        }
        out0 = a0 / s0 + b0;
        out1 = a1 / s1 + b1;
        out2 = a2 / s2 + b2;
    }
    if (do_relu) {
        out0 = fmaxf(out0, 0.f); out1 = fmaxf(out1, 0.f); out2 = fmaxf(out2, 0.f);
    }
    float* o = g_h + (size_t)gw * 96;
    o[lane] = out0; o[lane + 32] = out1; o[lane + 64] = out2;
}

// ---------------- per-node P = h@Wp_top, Q = h@Wp_bot + bp ----------------
__global__ void k_pq(const float* __restrict__ Wp, const float* __restrict__ bp, int n) {
    __shared__ float sW[1920];
    __shared__ float sb[10];
    for (int i = threadIdx.x; i < 1920; i += blockDim.x) sW[i] = Wp[i];
    if (threadIdx.x < 10) sb[threadIdx.x] = bp[threadIdx.x];
    __syncthreads();
    int t = blockIdx.x * blockDim.x + threadIdx.x;
    if (t >= n * 10) return;
    int node = t / 10, c = t % 10;
    const float* hr = g_h + (size_t)node * 96;
    float p = 0.f, q = 0.f;
    #pragma unroll 4
    for (int j = 0; j < 96; j++) {
        float hv = hr[j];
        p = fmaf(hv, sW[j * 10 + c], p);
        q = fmaf(hv, sW[(96 + j) * 10 + c], q);
    }
    g_P[t] = p;
    g_Q[t] = q + sb[c];
}

// ---------------- score[e,:] = P[src] + Q[dst] ----------------
__global__ void k_score(const int* __restrict__ src, const int* __restrict__ dst,
                        float* __restrict__ out, int e) {
    __shared__ float sm[2560];
    int tid = threadIdx.x;
    int eb = blockIdx.x * 256;
    int ed = eb + tid;
    if (ed < e) {
        int sn = src[ed], dn = dst[ed];
        #pragma unroll
        for (int c = 0; c < 10; c++)
            sm[tid * 10 + c] = g_P[sn * 10 + c] + g_Q[dn * 10 + c];
    }
    __syncthreads();
    int cnt = (e - eb < 256 ? e - eb : 256) * 10;
    for (int i = tid; i < cnt; i += 256)
        out[(size_t)eb * 10 + i] = sm[i];
}

// ---------------- driver: three-stream DAG ----------------
extern "C" void kernel_launch(void* const* d_in, const int* in_sizes, int n_in,
                              void* d_out, int out_size) {
    const float* nfeats = (const float*)d_in[0];
    const float* efeats = (const float*)d_in[1];
    const int*   src    = (const int*)  d_in[2];
    const int*   dst    = (const int*)  d_in[3];
    const float* W1  = (const float*)d_in[4];
    const float* We1 = (const float*)d_in[5];
    const float* al1 = (const float*)d_in[6];
    const float* ar1 = (const float*)d_in[7];
    const float* ae1 = (const float*)d_in[8];
    const float* b1  = (const float*)d_in[9];
    const float* W2  = (const float*)d_in[10];
    const float* We2 = (const float*)d_in[11];
    const float* al2 = (const float*)d_in[12];
    const float* ar2 = (const float*)d_in[13];
    const float* ae2 = (const float*)d_in[14];
    const float* b2  = (const float*)d_in[15];
    const float* Wp  = (const float*)d_in[16];
    const float* bp  = (const float*)d_in[17];
    float* out = (float*)d_out;

    int n = in_sizes[0] / 64;   // 100000
    int e = in_sizes[2];        // 1600000

    int eb   = (e + 255) / 256;
    int nb   = (n + 255) / 256;
    int nwb  = (n + 7) / 8;
    int ngb  = (n + 63) / 64;
    int nb1k = (n + 1023) / 1024;

    static cudaStream_t s1 = nullptr, s2 = nullptr;
    static cudaEvent_t evFork = nullptr, evVe = nullptr, evCsr = nullptr, evEe = nullptr;
    if (s1 == nullptr) {
        cudaStreamCreateWithFlags(&s1, cudaStreamNonBlocking);
        cudaStreamCreateWithFlags(&s2, cudaStreamNonBlocking);
        cudaEventCreateWithFlags(&evFork, cudaEventDisableTiming);
        cudaEventCreateWithFlags(&evVe,   cudaEventDisableTiming);
        cudaEventCreateWithFlags(&evCsr,  cudaEventDisableTiming);
        cudaEventCreateWithFlags(&evEe,   cudaEventDisableTiming);
    }

    // fork
    cudaEventRecord(evFork, 0);
    cudaStreamWaitEvent(s1, evFork, 0);

    // s1: CSR build
    k_zero_deg<<<nb, 256, 0, s1>>>(n);
    k_deg<<<eb, 256, 0, s1>>>(dst, e);
    k_scan1<<<nb1k, 1024, 0, s1>>>(n);
    k_scan2<<<1, 128, 0, s1>>>(nb1k);
    k_scan3<<<nb1k, 1024, 0, s1>>>(n, e);
    k_scatter<<<eb, 256, 0, s1>>>(src, dst, e);
    cudaEventRecord(evCsr, s1);

    // main: ve -> (s2: eepre) || wgemm64
    k_ve<<<1, 192>>>(We1, ae1, We2, ae2);
    cudaEventRecord(evVe, 0);
    cudaStreamWaitEvent(s2, evVe, 0);
    k_eepre<<<eb, 256, 0, s2>>>(efeats, e);
    cudaEventRecord(evEe, s2);

    k_wgemm<64><<<ngb, 256>>>(nfeats, W1, al1, ar1, n);

    // join
    cudaStreamWaitEvent(0, evCsr, 0);
    cudaStreamWaitEvent(0, evEe, 0);

    // layer 1
    k_combine<<<eb, 256>>>(src, dst, e);
    k_conv<<<nwb, 256>>>(b1, n, 1);

    // layer 2
    k_wgemm<96><<<ngb, 256>>>(nullptr, W2, al2, ar2, n);
    k_wc2<<<eb, 256>>>(e);
    k_conv<<<nwb, 256>>>(b2, n, 0);

    // edge score head
    k_pq<<<(n * 10 + 255) / 256, 256>>>(Wp, bp, n);
    k_score<<<eb, 256>>>(src, dst, out, e);
}

// round 12
// speedup vs baseline: 1.0168x; 1.0168x over previous
#include <cuda_runtime.h>
#include <cuda_fp16.h>
#include <mma.h>
#include <math.h>

#define MAXN 100000
#define MAXE 1600000
typedef unsigned long long u64;
using namespace nvcuda;

// ---------------- scratch ----------------
__device__ float  g_ft[MAXN * 96];
__device__ float  g_h [MAXN * 96];
__device__ float4 g_el4[MAXN];
__device__ float4 g_er4[MAXN];
__device__ float4 g_eepA[MAXE];      // layer-1 ee terms, edge order
__device__ float4 g_eepB[MAXE];      // layer-2 ee terms, edge order
__device__ float4 g_eec24[MAXE];     // layer-2 ee terms, CSR order
__device__ float4 g_wc4[MAXE];       // exp weights (x0,x1,x2,0), CSR order
__device__ int    g_srcc[MAXE];
__device__ int    g_dstc[MAXE];
__device__ int    g_pos [MAXE];
__device__ int    g_deg [MAXN];
__device__ int    g_off [MAXN + 1];
__device__ int    g_woff[MAXN];
__device__ int    g_bsum[128];
__device__ int    g_boff[128];
__device__ float  g_P[MAXN * 12];    // padded rows: 3x float4 per node
__device__ float  g_Q[MAXN * 12];
__device__ float  g_Ve[2][32][3];

__device__ __forceinline__ float leaky(float w) { return (w > 0.f) ? w : 0.2f * w; }

// ---------------- K0: fold We @ ae for both layers ----------------
__global__ void k_ve(const float* __restrict__ We1, const float* __restrict__ ae1,
                     const float* __restrict__ We2, const float* __restrict__ ae2) {
    int t = threadIdx.x;
    if (t >= 192) return;
    int c = t / 96, r = t % 96, d = r / 3, h = r % 3;
    const float* We = c ? We2 : We1;
    const float* ae = c ? ae2 : ae1;
    float s = 0.f;
    #pragma unroll
    for (int f = 0; f < 32; f++) s = fmaf(We[d * 96 + h * 32 + f], ae[h * 32 + f], s);
    g_Ve[c][d][h] = s;
}

// ---------------- node transform: wmma fp16 GEMM (fp32 accum) ----------------------
template <int K>
__global__ void __launch_bounds__(256)
k_wgemm(const float* __restrict__ in,    // nullptr => read g_h
        const float* __restrict__ W,
        const float* __restrict__ al, const float* __restrict__ ar,
        int n) {
    constexpr int AP = K + 8;
    constexpr int ABYTES = 64 * AP * 2;
    constexpr int BBYTES = K * 96 * 2;
    constexpr int OBYTES = 64 * 100 * 4;
    constexpr int SBYTES = (ABYTES + BBYTES > OBYTES) ? (ABYTES + BBYTES) : OBYTES;
    __shared__ __align__(16) char raw[SBYTES];
    __half* sA = (__half*)raw;                   // [64][AP]
    __half* sB = (__half*)(raw + ABYTES);        // [K][96]
    float*  Os = (float*)raw;                    // [64][100] (overlays after compute)
    __shared__ float sal[96], sar[96];

    int tid = threadIdx.x;
    if (tid < 96) { sal[tid] = al[tid]; sar[tid] = ar[tid]; }

    int nb = blockIdx.x * 64;
    const float* base = in ? in : g_h;

    for (int i = tid; i < 64 * (K / 4); i += 256) {
        int row = i / (K / 4), kq = i % (K / 4);
        int gr = nb + row; if (gr >= n) gr = n - 1;
        float4 v = ((const float4*)(base + (size_t)gr * K))[kq];
        __half* d = sA + row * AP + kq * 4;
        d[0] = __float2half(v.x); d[1] = __float2half(v.y);
        d[2] = __float2half(v.z); d[3] = __float2half(v.w);
    }
    for (int i = tid; i < K * 24; i += 256) {
        float4 v = ((const float4*)W)[i];
        __half* d = sB + i * 4;
        d[0] = __float2half(v.x); d[1] = __float2half(v.y);
        d[2] = __float2half(v.z); d[3] = __float2half(v.w);
    }
    __syncthreads();

    int wid = tid >> 5;
    int mt  = wid & 3;
    int ng  = (wid >> 2) * 3;

    wmma::fragment<wmma::accumulator, 16, 16, 16, float> c[3];
    #pragma unroll
    for (int j = 0; j < 3; j++) wmma::fill_fragment(c[j], 0.f);

    #pragma unroll
    for (int kt = 0; kt < K / 16; kt++) {
        wmma::fragment<wmma::matrix_a, 16, 16, 16, __half, wmma::row_major> a;
        wmma::load_matrix_sync(a, sA + mt * 16 * AP + kt * 16, AP);
        #pragma unroll
        for (int j = 0; j < 3; j++) {
            wmma::fragment<wmma::matrix_b, 16, 16, 16, __half, wmma::row_major> b;
            wmma::load_matrix_sync(b, sB + kt * 16 * 96 + (ng + j) * 16, 96);
            wmma::mma_sync(c[j], a, b, c[j]);
        }
    }
    __syncthreads();

    #pragma unroll
    for (int j = 0; j < 3; j++)
        wmma::store_matrix_sync(Os + mt * 16 * 100 + (ng + j) * 16, c[j], 100, wmma::mem_row_major);
    __syncthreads();

    // fp32 ft store
    for (int i = tid; i < 64 * 32; i += 256) {
        int nl = i >> 5, j0 = i & 31;
        int node = nb + nl;
        if (node < n) {
            const float* orow = Os + nl * 100;
            float* fo = g_ft + (size_t)node * 96;
            fo[j0]      = orow[j0];
            fo[j0 + 32] = orow[j0 + 32];
            fo[j0 + 64] = orow[j0 + 64];
        }
    }
    // el/er: 64 threads, one node each
    if (tid < 64 && nb + tid < n) {
        const float4* orow = (const float4*)(Os + tid * 100);
        float el[3] = {0.f, 0.f, 0.f}, er[3] = {0.f, 0.f, 0.f};
        #pragma unroll
        for (int q = 0; q < 24; q++) {
            float4 v = orow[q];
            float xs[4] = {v.x, v.y, v.z, v.w};
            #pragma unroll
            for (int j = 0; j < 4; j++) {
                int cix = q * 4 + j, h = cix >> 5;
                el[h] = fmaf(xs[j], sal[cix], el[h]);
                er[h] = fmaf(xs[j], sar[cix], er[h]);
            }
        }
        g_el4[nb + tid] = make_float4(el[0], el[1], el[2], 0.f);
        g_er4[nb + tid] = make_float4(er[0], er[1], er[2], 0.f);
    }
}

// ---------------- eepre: efeats GEMV only (edge order; needs only Ve) --------------
__global__ void k_eepre(const float* __restrict__ ef, int e_cnt) {
    __shared__ float sVe[192];
    if (threadIdx.x < 192) sVe[threadIdx.x] = ((const float*)g_Ve)[threadIdx.x];
    __syncthreads();
    int e = blockIdx.x * blockDim.x + threadIdx.x;
    if (e >= e_cnt) return;
    const float4* p = (const float4*)(ef + (size_t)e * 32);
    float acc0 = 0, acc1 = 0, acc2 = 0, acc3 = 0, acc4 = 0, acc5 = 0;
    #pragma unroll
    for (int q = 0; q < 8; q++) {
        float4 v = p[q];
        float xs[4] = {v.x, v.y, v.z, v.w};
        #pragma unroll
        for (int j = 0; j < 4; j++) {
            int d = q * 4 + j;
            float x = xs[j];
            acc0 = fmaf(x, sVe[d * 3 + 0],      acc0);
            acc1 = fmaf(x, sVe[d * 3 + 1],      acc1);
            acc2 = fmaf(x, sVe[d * 3 + 2],      acc2);
            acc3 = fmaf(x, sVe[96 + d * 3 + 0], acc3);
            acc4 = fmaf(x, sVe[96 + d * 3 + 1], acc4);
            acc5 = fmaf(x, sVe[96 + d * 3 + 2], acc5);
        }
    }
    g_eepA[e] = make_float4(acc0, acc1, acc2, 0.f);
    g_eepB[e] = make_float4(acc3, acc4, acc5, 0.f);
}

// ---------------- combine: el/er gather + exp, scatter to CSR ----------------------
__global__ void k_combine(const int* __restrict__ src, const int* __restrict__ dst,
                          int e_cnt) {
    int e = blockIdx.x * blockDim.x + threadIdx.x;
    if (e >= e_cnt) return;
    float4 A = g_eepA[e];
    int sn = src[e], dn = dst[e];
    float4 el = g_el4[sn];
    float4 er = g_er4[dn];
    float x0 = __expf(leaky(el.x + er.x + A.x));
    float x1 = __expf(leaky(el.y + er.y + A.y));
    float x2 = __expf(leaky(el.z + er.z + A.z));
    int pp = g_pos[e];
    g_wc4[pp]   = make_float4(x0, x1, x2, 0.f);
    g_eec24[pp] = g_eepB[e];
}

// ---------------- layer-2 exp weights: edge-parallel over CSR slots ----------------
__global__ void k_wc2(int e_cnt) {
    int i = blockIdx.x * blockDim.x + threadIdx.x;
    if (i >= e_cnt) return;
    int sn = g_srcc[i], dn = g_dstc[i];
    float4 el = g_el4[sn];
    float4 er = g_er4[dn];
    float4 ee = g_eec24[i];
    float x0 = __expf(leaky(el.x + er.x + ee.x));
    float x1 = __expf(leaky(el.y + er.y + ee.y));
    float x2 = __expf(leaky(el.z + er.z + ee.z));
    g_wc4[i] = make_float4(x0, x1, x2, 0.f);
}

// ---------------- CSR build ----------------
__global__ void k_zero_deg(int n) {
    int i = blockIdx.x * blockDim.x + threadIdx.x;
    if (i < n) g_deg[i] = 0;
}
__global__ void k_deg(const int* __restrict__ dst, int e) {
    int i = blockIdx.x * blockDim.x + threadIdx.x;
    if (i < e) atomicAdd(&g_deg[dst[i]], 1);
}
__global__ void k_scan1(int n) {
    __shared__ int s[1024];
    int idx = blockIdx.x * 1024 + threadIdx.x;
    int v = (idx < n) ? g_deg[idx] : 0;
    s[threadIdx.x] = v;
    __syncthreads();
    #pragma unroll
    for (int off = 1; off < 1024; off <<= 1) {
        int t = (threadIdx.x >= off) ? s[threadIdx.x - off] : 0;
        __syncthreads();
        s[threadIdx.x] += t;
        __syncthreads();
    }
    if (idx < n) g_off[idx] = s[threadIdx.x] - v;
    if (threadIdx.x == 1023) g_bsum[blockIdx.x] = s[1023];
}
__global__ void k_scan2(int nb) {
    __shared__ int s[128];
    int tid = threadIdx.x;
    int v = (tid < nb) ? g_bsum[tid] : 0;
    s[tid] = v;
    __syncthreads();
    #pragma unroll
    for (int off = 1; off < 128; off <<= 1) {
        int t = (tid >= off) ? s[tid - off] : 0;
        __syncthreads();
        s[tid] += t;
        __syncthreads();
    }
    if (tid < nb) g_boff[tid] = s[tid] - v;
}
__global__ void k_scan3(int n, int e) {
    int idx = blockIdx.x * 1024 + threadIdx.x;
    if (idx < n) {
        int o = g_off[idx] + g_boff[blockIdx.x];
        g_off[idx] = o;
        g_woff[idx] = o;
    }
    if (idx == 0) g_off[n] = e;
}
__global__ void k_scatter(const int* __restrict__ src, const int* __restrict__ dst, int e) {
    int i = blockIdx.x * blockDim.x + threadIdx.x;
    if (i < e) {
        int d = dst[i];
        int p = atomicAdd(&g_woff[d], 1);
        g_srcc[p] = src[i];
        g_dstc[p] = d;
        g_pos[i] = p;
    }
}

// ---------------- conv: single sweep, fp32 ft gather (R9-proven) -------------------
__global__ void k_conv(const float* __restrict__ bias, int n, int do_relu) {
    int gw   = (blockIdx.x * blockDim.x + threadIdx.x) >> 5;
    int lane = threadIdx.x & 31;
    if (gw >= n) return;
    int beg = g_off[gw], end = g_off[gw + 1];
    float b0 = bias[lane], b1 = bias[lane + 32], b2 = bias[lane + 64];
    float out0, out1, out2;
    if (beg == end) {
        out0 = b0; out1 = b1; out2 = b2;
    } else {
        float s0 = 0.f, s1 = 0.f, s2 = 0.f;
        float a0 = 0.f, a1 = 0.f, a2 = 0.f;
        #pragma unroll 8
        for (int i = beg; i < end; i++) {
            float4 x = g_wc4[i];
            int sn = g_srcc[i];
            const float* fr = g_ft + (size_t)sn * 96;
            a0 = fmaf(x.x, fr[lane],      a0);
            a1 = fmaf(x.y, fr[lane + 32], a1);
            a2 = fmaf(x.z, fr[lane + 64], a2);
            s0 += x.x; s1 += x.y; s2 += x.z;
        }
        out0 = a0 / s0 + b0;
        out1 = a1 / s1 + b1;
        out2 = a2 / s2 + b2;
    }
    if (do_relu) {
        out0 = fmaxf(out0, 0.f); out1 = fmaxf(out1, 0.f); out2 = fmaxf(out2, 0.f);
    }
    float* o = g_h + (size_t)gw * 96;
    o[lane] = out0; o[lane + 32] = out1; o[lane + 64] = out2;
}

// ---------------- per-node P = h@Wp_top, Q = h@Wp_bot + bp (padded rows) -----------
__global__ void k_pq(const float* __restrict__ Wp, const float* __restrict__ bp, int n) {
    __shared__ float sW[1920];
    __shared__ float sb[10];
    for (int i = threadIdx.x; i < 1920; i += blockDim.x) sW[i] = Wp[i];
    if (threadIdx.x < 10) sb[threadIdx.x] = bp[threadIdx.x];
    __syncthreads();
    int t = blockIdx.x * blockDim.x + threadIdx.x;
    if (t >= n * 10) return;
    int node = t / 10, c = t % 10;
    const float* hr = g_h + (size_t)node * 96;
    float p = 0.f, q = 0.f;
    #pragma unroll 4
    for (int j = 0; j < 96; j++) {
        float hv = hr[j];
        p = fmaf(hv, sW[j * 10 + c], p);
        q = fmaf(hv, sW[(96 + j) * 10 + c], q);
    }
    g_P[node * 12 + c] = p;
    g_Q[node * 12 + c] = q + sb[c];
}

// ---------------- score[e,:] = P[src] + Q[dst]; float4 gathers ---------------------
__global__ void k_score(const int* __restrict__ src, const int* __restrict__ dst,
                        float* __restrict__ out, int e) {
    __shared__ float sm[2560];
    int tid = threadIdx.x;
    int eb = blockIdx.x * 256;
    int ed = eb + tid;
    if (ed < e) {
        int sn = src[ed], dn = dst[ed];
        const float4* P4 = (const float4*)(g_P + sn * 12);
        const float4* Q4 = (const float4*)(g_Q + dn * 12);
        float4 p0 = P4[0], p1 = P4[1], p2 = P4[2];
        float4 q0 = Q4[0], q1 = Q4[1], q2 = Q4[2];
        float* s = sm + tid * 10;
        s[0] = p0.x + q0.x; s[1] = p0.y + q0.y; s[2] = p0.z + q0.z; s[3] = p0.w + q0.w;
        s[4] = p1.x + q1.x; s[5] = p1.y + q1.y; s[6] = p1.z + q1.z; s[7] = p1.w + q1.w;
        s[8] = p2.x + q2.x; s[9] = p2.y + q2.y;
    }
    __syncthreads();
    int cnt = (e - eb < 256 ? e - eb : 256) * 10;
    for (int i = tid; i < cnt; i += 256)
        out[(size_t)eb * 10 + i] = sm[i];
}

// ---------------- driver: three-stream DAG ----------------
extern "C" void kernel_launch(void* const* d_in, const int* in_sizes, int n_in,
                              void* d_out, int out_size) {
    const float* nfeats = (const float*)d_in[0];
    const float* efeats = (const float*)d_in[1];
    const int*   src    = (const int*)  d_in[2];
    const int*   dst    = (const int*)  d_in[3];
    const float* W1  = (const float*)d_in[4];
    const float* We1 = (const float*)d_in[5];
    const float* al1 = (const float*)d_in[6];
    const float* ar1 = (const float*)d_in[7];
    const float* ae1 = (const float*)d_in[8];
    const float* b1  = (const float*)d_in[9];
    const float* W2  = (const float*)d_in[10];
    const float* We2 = (const float*)d_in[11];
    const float* al2 = (const float*)d_in[12];
    const float* ar2 = (const float*)d_in[13];
    const float* ae2 = (const float*)d_in[14];
    const float* b2  = (const float*)d_in[15];
    const float* Wp  = (const float*)d_in[16];
    const float* bp  = (const float*)d_in[17];
    float* out = (float*)d_out;

    int n = in_sizes[0] / 64;   // 100000
    int e = in_sizes[2];        // 1600000

    int eb   = (e + 255) / 256;
    int nb   = (n + 255) / 256;
    int nwb  = (n + 7) / 8;
    int ngb  = (n + 63) / 64;
    int nb1k = (n + 1023) / 1024;

    static cudaStream_t s1 = nullptr, s2 = nullptr;
    static cudaEvent_t evFork = nullptr, evVe = nullptr, evCsr = nullptr, evEe = nullptr;
    if (s1 == nullptr) {
        cudaStreamCreateWithFlags(&s1, cudaStreamNonBlocking);
        cudaStreamCreateWithFlags(&s2, cudaStreamNonBlocking);
        cudaEventCreateWithFlags(&evFork, cudaEventDisableTiming);
        cudaEventCreateWithFlags(&evVe,   cudaEventDisableTiming);
        cudaEventCreateWithFlags(&evCsr,  cudaEventDisableTiming);
        cudaEventCreateWithFlags(&evEe,   cudaEventDisableTiming);
    }

    // fork
    cudaEventRecord(evFork, 0);
    cudaStreamWaitEvent(s1, evFork, 0);

    // s1: CSR build
    k_zero_deg<<<nb, 256, 0, s1>>>(n);
    k_deg<<<eb, 256, 0, s1>>>(dst, e);
    k_scan1<<<nb1k, 1024, 0, s1>>>(n);
    k_scan2<<<1, 128, 0, s1>>>(nb1k);
    k_scan3<<<nb1k, 1024, 0, s1>>>(n, e);
    k_scatter<<<eb, 256, 0, s1>>>(src, dst, e);
    cudaEventRecord(evCsr, s1);

    // main: ve -> (s2: eepre) || wgemm64
    k_ve<<<1, 192>>>(We1, ae1, We2, ae2);
    cudaEventRecord(evVe, 0);
    cudaStreamWaitEvent(s2, evVe, 0);
    k_eepre<<<eb, 256, 0, s2>>>(efeats, e);
    cudaEventRecord(evEe, s2);

    k_wgemm<64><<<ngb, 256>>>(nfeats, W1, al1, ar1, n);

    // join
    cudaStreamWaitEvent(0, evCsr, 0);
    cudaStreamWaitEvent(0, evEe, 0);

    // layer 1
    k_combine<<<eb, 256>>>(src, dst, e);
    k_conv<<<nwb, 256>>>(b1, n, 1);

    // layer 2
    k_wgemm<96><<<ngb, 256>>>(nullptr, W2, al2, ar2, n);
    k_wc2<<<eb, 256>>>(e);
    k_conv<<<nwb, 256>>>(b2, n, 0);

    // edge score head
    k_pq<<<(n * 10 + 255) / 256, 256>>>(Wp, bp, n);
    k_score<<<eb, 256>>>(src, dst, out, e);
}

// round 13
// speedup vs baseline: 1.0713x; 1.0536x over previous
#include <cuda_runtime.h>
#include <cuda_fp16.h>
#include <mma.h>
#include <math.h>

#define MAXN 100000
#define MAXE 1600000
typedef unsigned long long u64;
using namespace nvcuda;

// ---------------- scratch ----------------
__device__ float  g_ft[MAXN * 96];
__device__ float  g_h [MAXN * 96];
__device__ float4 g_el4[MAXN];
__device__ float4 g_er4[MAXN];
__device__ float4 g_eepA[MAXE];      // layer-1 ee terms, edge order
__device__ float4 g_eepB[MAXE];      // layer-2 ee terms, edge order
__device__ float4 g_eec24[MAXE];     // layer-2 ee terms, CSR order
__device__ float4 g_wc4[MAXE];       // exp weights (x0,x1,x2,0), CSR order
__device__ int    g_srcc[MAXE];
__device__ int    g_dstc[MAXE];
__device__ int    g_pos [MAXE];
__device__ int    g_deg [MAXN];
__device__ int    g_off [MAXN + 1];
__device__ int    g_woff[MAXN];
__device__ int    g_bsum[128];
__device__ int    g_boff[128];
__device__ float  g_P[MAXN * 12];    // padded rows: 3x float4 per node
__device__ float  g_Q[MAXN * 12];
__device__ float  g_Ve[2][32][3];

__device__ __forceinline__ float leaky(float w) { return (w > 0.f) ? w : 0.2f * w; }

// ---------------- K0: fold We @ ae for both layers ----------------
__global__ void k_ve(const float* __restrict__ We1, const float* __restrict__ ae1,
                     const float* __restrict__ We2, const float* __restrict__ ae2) {
    int t = threadIdx.x;
    if (t >= 192) return;
    int c = t / 96, r = t % 96, d = r / 3, h = r % 3;
    const float* We = c ? We2 : We1;
    const float* ae = c ? ae2 : ae1;
    float s = 0.f;
    #pragma unroll
    for (int f = 0; f < 32; f++) s = fmaf(We[d * 96 + h * 32 + f], ae[h * 32 + f], s);
    g_Ve[c][d][h] = s;
}

// ---------------- node transform: wmma fp16 GEMM (fp32 accum) ----------------------
template <int K>
__global__ void __launch_bounds__(256)
k_wgemm(const float* __restrict__ in,    // nullptr => read g_h
        const float* __restrict__ W,
        const float* __restrict__ al, const float* __restrict__ ar,
        int n) {
    constexpr int AP = K + 8;
    constexpr int ABYTES = 64 * AP * 2;
    constexpr int BBYTES = K * 96 * 2;
    constexpr int OBYTES = 64 * 100 * 4;
    constexpr int SBYTES = (ABYTES + BBYTES > OBYTES) ? (ABYTES + BBYTES) : OBYTES;
    __shared__ __align__(16) char raw[SBYTES];
    __half* sA = (__half*)raw;                   // [64][AP]
    __half* sB = (__half*)(raw + ABYTES);        // [K][96]
    float*  Os = (float*)raw;                    // [64][100] (overlays after compute)
    __shared__ float sal[96], sar[96];

    int tid = threadIdx.x;
    if (tid < 96) { sal[tid] = al[tid]; sar[tid] = ar[tid]; }

    int nb = blockIdx.x * 64;
    const float* base = in ? in : g_h;

    for (int i = tid; i < 64 * (K / 4); i += 256) {
        int row = i / (K / 4), kq = i % (K / 4);
        int gr = nb + row; if (gr >= n) gr = n - 1;
        float4 v = ((const float4*)(base + (size_t)gr * K))[kq];
        __half* d = sA + row * AP + kq * 4;
        d[0] = __float2half(v.x); d[1] = __float2half(v.y);
        d[2] = __float2half(v.z); d[3] = __float2half(v.w);
    }
    for (int i = tid; i < K * 24; i += 256) {
        float4 v = ((const float4*)W)[i];
        __half* d = sB + i * 4;
        d[0] = __float2half(v.x); d[1] = __float2half(v.y);
        d[2] = __float2half(v.z); d[3] = __float2half(v.w);
    }
    __syncthreads();

    int wid = tid >> 5;
    int mt  = wid & 3;
    int ng  = (wid >> 2) * 3;

    wmma::fragment<wmma::accumulator, 16, 16, 16, float> c[3];
    #pragma unroll
    for (int j = 0; j < 3; j++) wmma::fill_fragment(c[j], 0.f);

    #pragma unroll
    for (int kt = 0; kt < K / 16; kt++) {
        wmma::fragment<wmma::matrix_a, 16, 16, 16, __half, wmma::row_major> a;
        wmma::load_matrix_sync(a, sA + mt * 16 * AP + kt * 16, AP);
        #pragma unroll
        for (int j = 0; j < 3; j++) {
            wmma::fragment<wmma::matrix_b, 16, 16, 16, __half, wmma::row_major> b;
            wmma::load_matrix_sync(b, sB + kt * 16 * 96 + (ng + j) * 16, 96);
            wmma::mma_sync(c[j], a, b, c[j]);
        }
    }
    __syncthreads();

    #pragma unroll
    for (int j = 0; j < 3; j++)
        wmma::store_matrix_sync(Os + mt * 16 * 100 + (ng + j) * 16, c[j], 100, wmma::mem_row_major);
    __syncthreads();

    // fp32 ft store
    for (int i = tid; i < 64 * 32; i += 256) {
        int nl = i >> 5, j0 = i & 31;
        int node = nb + nl;
        if (node < n) {
            const float* orow = Os + nl * 100;
            float* fo = g_ft + (size_t)node * 96;
            fo[j0]      = orow[j0];
            fo[j0 + 32] = orow[j0 + 32];
            fo[j0 + 64] = orow[j0 + 64];
        }
    }
    // el/er: 64 threads, one node each
    if (tid < 64 && nb + tid < n) {
        const float4* orow = (const float4*)(Os + tid * 100);
        float el[3] = {0.f, 0.f, 0.f}, er[3] = {0.f, 0.f, 0.f};
        #pragma unroll
        for (int q = 0; q < 24; q++) {
            float4 v = orow[q];
            float xs[4] = {v.x, v.y, v.z, v.w};
            #pragma unroll
            for (int j = 0; j < 4; j++) {
                int cix = q * 4 + j, h = cix >> 5;
                el[h] = fmaf(xs[j], sal[cix], el[h]);
                er[h] = fmaf(xs[j], sar[cix], er[h]);
            }
        }
        g_el4[nb + tid] = make_float4(el[0], el[1], el[2], 0.f);
        g_er4[nb + tid] = make_float4(er[0], er[1], er[2], 0.f);
    }
}

// ---------------- eepre: efeats GEMV only (edge order; needs only Ve) --------------
__global__ void k_eepre(const float* __restrict__ ef, int e_cnt) {
    __shared__ float sVe[192];
    if (threadIdx.x < 192) sVe[threadIdx.x] = ((const float*)g_Ve)[threadIdx.x];
    __syncthreads();
    int e = blockIdx.x * blockDim.x + threadIdx.x;
    if (e >= e_cnt) return;
    const float4* p = (const float4*)(ef + (size_t)e * 32);
    float acc0 = 0, acc1 = 0, acc2 = 0, acc3 = 0, acc4 = 0, acc5 = 0;
    #pragma unroll
    for (int q = 0; q < 8; q++) {
        float4 v = p[q];
        float xs[4] = {v.x, v.y, v.z, v.w};
        #pragma unroll
        for (int j = 0; j < 4; j++) {
            int d = q * 4 + j;
            float x = xs[j];
            acc0 = fmaf(x, sVe[d * 3 + 0],      acc0);
            acc1 = fmaf(x, sVe[d * 3 + 1],      acc1);
            acc2 = fmaf(x, sVe[d * 3 + 2],      acc2);
            acc3 = fmaf(x, sVe[96 + d * 3 + 0], acc3);
            acc4 = fmaf(x, sVe[96 + d * 3 + 1], acc4);
            acc5 = fmaf(x, sVe[96 + d * 3 + 2], acc5);
        }
    }
    g_eepA[e] = make_float4(acc0, acc1, acc2, 0.f);
    g_eepB[e] = make_float4(acc3, acc4, acc5, 0.f);
}

// ---------------- combine: el/er gather + exp, scatter to CSR ----------------------
__global__ void k_combine(const int* __restrict__ src, const int* __restrict__ dst,
                          int e_cnt) {
    int e = blockIdx.x * blockDim.x + threadIdx.x;
    if (e >= e_cnt) return;
    float4 A = g_eepA[e];
    int sn = src[e], dn = dst[e];
    float4 el = g_el4[sn];
    float4 er = g_er4[dn];
    float x0 = __expf(leaky(el.x + er.x + A.x));
    float x1 = __expf(leaky(el.y + er.y + A.y));
    float x2 = __expf(leaky(el.z + er.z + A.z));
    int pp = g_pos[e];
    g_wc4[pp]   = make_float4(x0, x1, x2, 0.f);
    g_eec24[pp] = g_eepB[e];
}

// ---------------- layer-2 exp weights: edge-parallel over CSR slots ----------------
__global__ void k_wc2(int e_cnt) {
    int i = blockIdx.x * blockDim.x + threadIdx.x;
    if (i >= e_cnt) return;
    int sn = g_srcc[i], dn = g_dstc[i];
    float4 el = g_el4[sn];
    float4 er = g_er4[dn];
    float4 ee = g_eec24[i];
    float x0 = __expf(leaky(el.x + er.x + ee.x));
    float x1 = __expf(leaky(el.y + er.y + ee.y));
    float x2 = __expf(leaky(el.z + er.z + ee.z));
    g_wc4[i] = make_float4(x0, x1, x2, 0.f);
}

// ---------------- CSR build ----------------
__global__ void k_zero_deg(int n) {
    int i = blockIdx.x * blockDim.x + threadIdx.x;
    if (i < n) g_deg[i] = 0;
}
__global__ void k_deg(const int* __restrict__ dst, int e) {
    int i = blockIdx.x * blockDim.x + threadIdx.x;
    if (i < e) atomicAdd(&g_deg[dst[i]], 1);
}
__global__ void k_scan1(int n) {
    __shared__ int s[1024];
    int idx = blockIdx.x * 1024 + threadIdx.x;
    int v = (idx < n) ? g_deg[idx] : 0;
    s[threadIdx.x] = v;
    __syncthreads();
    #pragma unroll
    for (int off = 1; off < 1024; off <<= 1) {
        int t = (threadIdx.x >= off) ? s[threadIdx.x - off] : 0;
        __syncthreads();
        s[threadIdx.x] += t;
        __syncthreads();
    }
    if (idx < n) g_off[idx] = s[threadIdx.x] - v;
    if (threadIdx.x == 1023) g_bsum[blockIdx.x] = s[1023];
}
__global__ void k_scan2(int nb) {
    __shared__ int s[128];
    int tid = threadIdx.x;
    int v = (tid < nb) ? g_bsum[tid] : 0;
    s[tid] = v;
    __syncthreads();
    #pragma unroll
    for (int off = 1; off < 128; off <<= 1) {
        int t = (tid >= off) ? s[tid - off] : 0;
        __syncthreads();
        s[tid] += t;
        __syncthreads();
    }
    if (tid < nb) g_boff[tid] = s[tid] - v;
}
__global__ void k_scan3(int n, int e) {
    int idx = blockIdx.x * 1024 + threadIdx.x;
    if (idx < n) {
        int o = g_off[idx] + g_boff[blockIdx.x];
        g_off[idx] = o;
        g_woff[idx] = o;
    }
    if (idx == 0) g_off[n] = e;
}
__global__ void k_scatter(const int* __restrict__ src, const int* __restrict__ dst, int e) {
    int i = blockIdx.x * blockDim.x + threadIdx.x;
    if (i < e) {
        int d = dst[i];
        int p = atomicAdd(&g_woff[d], 1);
        g_srcc[p] = src[i];
        g_dstc[p] = d;
        g_pos[i] = p;
    }
}

// ---------------- conv: single sweep; 64-thr blocks (2 warps) for load balance ----
__global__ void __launch_bounds__(64)
k_conv(const float* __restrict__ bias, int n, int do_relu) {
    int gw   = (blockIdx.x * blockDim.x + threadIdx.x) >> 5;
    int lane = threadIdx.x & 31;
    if (gw >= n) return;
    int beg = g_off[gw], end = g_off[gw + 1];
    float b0 = bias[lane], b1 = bias[lane + 32], b2 = bias[lane + 64];
    float out0, out1, out2;
    if (beg == end) {
        out0 = b0; out1 = b1; out2 = b2;
    } else {
        float s0 = 0.f, s1 = 0.f, s2 = 0.f;
        float a0 = 0.f, a1 = 0.f, a2 = 0.f;
        #pragma unroll 8
        for (int i = beg; i < end; i++) {
            float4 x = g_wc4[i];
            int sn = g_srcc[i];
            const float* fr = g_ft + (size_t)sn * 96;
            a0 = fmaf(x.x, fr[lane],      a0);
            a1 = fmaf(x.y, fr[lane + 32], a1);
            a2 = fmaf(x.z, fr[lane + 64], a2);
            s0 += x.x; s1 += x.y; s2 += x.z;
        }
        out0 = a0 / s0 + b0;
        out1 = a1 / s1 + b1;
        out2 = a2 / s2 + b2;
    }
    if (do_relu) {
        out0 = fmaxf(out0, 0.f); out1 = fmaxf(out1, 0.f); out2 = fmaxf(out2, 0.f);
    }
    float* o = g_h + (size_t)gw * 96;
    o[lane] = out0; o[lane + 32] = out1; o[lane + 64] = out2;
}

// ---------------- per-node P = h@Wp_top, Q = h@Wp_bot + bp (float4 reads) ----------
__global__ void k_pq(const float* __restrict__ Wp, const float* __restrict__ bp, int n) {
    __shared__ float sW[1920];
    __shared__ float sb[10];
    for (int i = threadIdx.x; i < 1920; i += blockDim.x) sW[i] = Wp[i];
    if (threadIdx.x < 10) sb[threadIdx.x] = bp[threadIdx.x];
    __syncthreads();
    int t = blockIdx.x * blockDim.x + threadIdx.x;
    if (t >= n * 10) return;
    int node = t / 10, c = t % 10;
    const float4* hr = (const float4*)(g_h + (size_t)node * 96);
    float p = 0.f, q = 0.f;
    #pragma unroll 6
    for (int jq = 0; jq < 24; jq++) {
        float4 v = hr[jq];
        float xs[4] = {v.x, v.y, v.z, v.w};
        #pragma unroll
        for (int u = 0; u < 4; u++) {
            int j = jq * 4 + u;
            p = fmaf(xs[u], sW[j * 10 + c], p);
            q = fmaf(xs[u], sW[(96 + j) * 10 + c], q);
        }
    }
    g_P[node * 12 + c] = p;
    g_Q[node * 12 + c] = q + sb[c];
}

// ---------------- score[e,:] = P[src] + Q[dst]; float4 gathers + float4 stores -----
__global__ void k_score(const int* __restrict__ src, const int* __restrict__ dst,
                        float* __restrict__ out, int e) {
    __shared__ float sm[2560];
    int tid = threadIdx.x;
    int eb = blockIdx.x * 256;
    int ed = eb + tid;
    if (ed < e) {
        int sn = src[ed], dn = dst[ed];
        const float4* P4 = (const float4*)(g_P + sn * 12);
        const float4* Q4 = (const float4*)(g_Q + dn * 12);
        float4 p0 = P4[0], p1 = P4[1], p2 = P4[2];
        float4 q0 = Q4[0], q1 = Q4[1], q2 = Q4[2];
        float* s = sm + tid * 10;
        s[0] = p0.x + q0.x; s[1] = p0.y + q0.y; s[2] = p0.z + q0.z; s[3] = p0.w + q0.w;
        s[4] = p1.x + q1.x; s[5] = p1.y + q1.y; s[6] = p1.z + q1.z; s[7] = p1.w + q1.w;
        s[8] = p2.x + q2.x; s[9] = p2.y + q2.y;
    }
    __syncthreads();
    int rem = e - eb;
    if (rem >= 256) {
        // full block: 2560 floats, 16B-aligned base (eb*10*4 % 16 == 0)
        float4* o4 = (float4*)(out + (size_t)eb * 10);
        const float4* s4 = (const float4*)sm;
        for (int i = tid; i < 640; i += 256) o4[i] = s4[i];
    } else {
        int cnt = rem * 10;
        for (int i = tid; i < cnt; i += 256)
            out[(size_t)eb * 10 + i] = sm[i];
    }
}

// ---------------- driver: three-stream DAG ----------------
extern "C" void kernel_launch(void* const* d_in, const int* in_sizes, int n_in,
                              void* d_out, int out_size) {
    const float* nfeats = (const float*)d_in[0];
    const float* efeats = (const float*)d_in[1];
    const int*   src    = (const int*)  d_in[2];
    const int*   dst    = (const int*)  d_in[3];
    const float* W1  = (const float*)d_in[4];
    const float* We1 = (const float*)d_in[5];
    const float* al1 = (const float*)d_in[6];
    const float* ar1 = (const float*)d_in[7];
    const float* ae1 = (const float*)d_in[8];
    const float* b1  = (const float*)d_in[9];
    const float* W2  = (const float*)d_in[10];
    const float* We2 = (const float*)d_in[11];
    const float* al2 = (const float*)d_in[12];
    const float* ar2 = (const float*)d_in[13];
    const float* ae2 = (const float*)d_in[14];
    const float* b2  = (const float*)d_in[15];
    const float* Wp  = (const float*)d_in[16];
    const float* bp  = (const float*)d_in[17];
    float* out = (float*)d_out;

    int n = in_sizes[0] / 64;   // 100000
    int e = in_sizes[2];        // 1600000

    int eb   = (e + 255) / 256;
    int nb   = (n + 255) / 256;
    int ncb  = (n + 1) / 2;          // conv: 64-thr blocks, 2 nodes each
    int ngb  = (n + 63) / 64;
    int nb1k = (n + 1023) / 1024;

    static cudaStream_t s1 = nullptr, s2 = nullptr;
    static cudaEvent_t evFork = nullptr, evVe = nullptr, evCsr = nullptr, evEe = nullptr;
    if (s1 == nullptr) {
        cudaStreamCreateWithFlags(&s1, cudaStreamNonBlocking);
        cudaStreamCreateWithFlags(&s2, cudaStreamNonBlocking);
        cudaEventCreateWithFlags(&evFork, cudaEventDisableTiming);
        cudaEventCreateWithFlags(&evVe,   cudaEventDisableTiming);
        cudaEventCreateWithFlags(&evCsr,  cudaEventDisableTiming);
        cudaEventCreateWithFlags(&evEe,   cudaEventDisableTiming);
    }

    // fork
    cudaEventRecord(evFork, 0);
    cudaStreamWaitEvent(s1, evFork, 0);

    // s1: CSR build
    k_zero_deg<<<nb, 256, 0, s1>>>(n);
    k_deg<<<eb, 256, 0, s1>>>(dst, e);
    k_scan1<<<nb1k, 1024, 0, s1>>>(n);
    k_scan2<<<1, 128, 0, s1>>>(nb1k);
    k_scan3<<<nb1k, 1024, 0, s1>>>(n, e);
    k_scatter<<<eb, 256, 0, s1>>>(src, dst, e);
    cudaEventRecord(evCsr, s1);

    // main: ve -> (s2: eepre) || wgemm64
    k_ve<<<1, 192>>>(We1, ae1, We2, ae2);
    cudaEventRecord(evVe, 0);
    cudaStreamWaitEvent(s2, evVe, 0);
    k_eepre<<<eb, 256, 0, s2>>>(efeats, e);
    cudaEventRecord(evEe, s2);

    k_wgemm<64><<<ngb, 256>>>(nfeats, W1, al1, ar1, n);

    // join
    cudaStreamWaitEvent(0, evCsr, 0);
    cudaStreamWaitEvent(0, evEe, 0);

    // layer 1
    k_combine<<<eb, 256>>>(src, dst, e);
    k_conv<<<ncb, 64>>>(b1, n, 1);

    // layer 2
    k_wgemm<96><<<ngb, 256>>>(nullptr, W2, al2, ar2, n);
    k_wc2<<<eb, 256>>>(e);
    k_conv<<<ncb, 64>>>(b2, n, 0);

    // edge score head
    k_pq<<<(n * 10 + 255) / 256, 256>>>(Wp, bp, n);
    k_score<<<eb, 256>>>(src, dst, out, e);
}

// round 14
// speedup vs baseline: 1.1004x; 1.0271x over previous
#include <cuda_runtime.h>
#include <cuda_fp16.h>
#include <mma.h>
#include <math.h>

#define MAXN 100000
#define MAXE 1600000
typedef unsigned long long u64;
using namespace nvcuda;

// ---------------- scratch ----------------
__device__ __half g_fth[MAXN * 96];  // ft in fp16, [node][96] (c, c+32, c+64 per lane)
__device__ float  g_h [MAXN * 96];
__device__ float4 g_el4[MAXN];
__device__ float4 g_er4[MAXN];
__device__ float4 g_eepA[MAXE];      // layer-1 ee terms, edge order
__device__ float4 g_eepB[MAXE];      // layer-2 ee terms, edge order
__device__ float4 g_eec24[MAXE];     // layer-2 ee terms, CSR order
__device__ float4 g_wc4[MAXE];       // exp weights (x0,x1,x2,0), CSR order
__device__ int    g_srcc[MAXE];
__device__ int    g_dstc[MAXE];
__device__ int    g_pos [MAXE];
__device__ int    g_deg [MAXN];
__device__ int    g_off [MAXN + 1];
__device__ int    g_woff[MAXN];
__device__ int    g_bsum[128];
__device__ int    g_boff[128];
__device__ float  g_P[MAXN * 12];    // padded rows: 3x float4 per node
__device__ float  g_Q[MAXN * 12];
__device__ float  g_Ve[2][32][3];

__device__ __forceinline__ float leaky(float w) { return (w > 0.f) ? w : 0.2f * w; }

// ---------------- K0: fold We @ ae for both layers ----------------
__global__ void k_ve(const float* __restrict__ We1, const float* __restrict__ ae1,
                     const float* __restrict__ We2, const float* __restrict__ ae2) {
    int t = threadIdx.x;
    if (t >= 192) return;
    int c = t / 96, r = t % 96, d = r / 3, h = r % 3;
    const float* We = c ? We2 : We1;
    const float* ae = c ? ae2 : ae1;
    float s = 0.f;
    #pragma unroll
    for (int f = 0; f < 32; f++) s = fmaf(We[d * 96 + h * 32 + f], ae[h * 32 + f], s);
    g_Ve[c][d][h] = s;
}

// ---------------- node transform: wmma fp16 GEMM (fp32 accum) ----------------------
template <int K>
__global__ void __launch_bounds__(256)
k_wgemm(const float* __restrict__ in,    // nullptr => read g_h
        const float* __restrict__ W,
        const float* __restrict__ al, const float* __restrict__ ar,
        int n) {
    constexpr int AP = K + 8;
    constexpr int ABYTES = 64 * AP * 2;
    constexpr int BBYTES = K * 96 * 2;
    constexpr int OBYTES = 64 * 100 * 4;
    constexpr int SBYTES = (ABYTES + BBYTES > OBYTES) ? (ABYTES + BBYTES) : OBYTES;
    __shared__ __align__(16) char raw[SBYTES];
    __half* sA = (__half*)raw;                   // [64][AP]
    __half* sB = (__half*)(raw + ABYTES);        // [K][96]
    float*  Os = (float*)raw;                    // [64][100] (overlays after compute)
    __shared__ float sal[96], sar[96];

    int tid = threadIdx.x;
    if (tid < 96) { sal[tid] = al[tid]; sar[tid] = ar[tid]; }

    int nb = blockIdx.x * 64;
    const float* base = in ? in : g_h;

    for (int i = tid; i < 64 * (K / 4); i += 256) {
        int row = i / (K / 4), kq = i % (K / 4);
        int gr = nb + row; if (gr >= n) gr = n - 1;
        float4 v = ((const float4*)(base + (size_t)gr * K))[kq];
        __half* d = sA + row * AP + kq * 4;
        d[0] = __float2half(v.x); d[1] = __float2half(v.y);
        d[2] = __float2half(v.z); d[3] = __float2half(v.w);
    }
    for (int i = tid; i < K * 24; i += 256) {
        float4 v = ((const float4*)W)[i];
        __half* d = sB + i * 4;
        d[0] = __float2half(v.x); d[1] = __float2half(v.y);
        d[2] = __float2half(v.z); d[3] = __float2half(v.w);
    }
    __syncthreads();

    int wid = tid >> 5;
    int mt  = wid & 3;
    int ng  = (wid >> 2) * 3;

    wmma::fragment<wmma::accumulator, 16, 16, 16, float> c[3];
    #pragma unroll
    for (int j = 0; j < 3; j++) wmma::fill_fragment(c[j], 0.f);

    #pragma unroll
    for (int kt = 0; kt < K / 16; kt++) {
        wmma::fragment<wmma::matrix_a, 16, 16, 16, __half, wmma::row_major> a;
        wmma::load_matrix_sync(a, sA + mt * 16 * AP + kt * 16, AP);
        #pragma unroll
        for (int j = 0; j < 3; j++) {
            wmma::fragment<wmma::matrix_b, 16, 16, 16, __half, wmma::row_major> b;
            wmma::load_matrix_sync(b, sB + kt * 16 * 96 + (ng + j) * 16, 96);
            wmma::mma_sync(c[j], a, b, c[j]);
        }
    }
    __syncthreads();

    #pragma unroll
    for (int j = 0; j < 3; j++)
        wmma::store_matrix_sync(Os + mt * 16 * 100 + (ng + j) * 16, c[j], 100, wmma::mem_row_major);
    __syncthreads();

    // ft store in fp16 ([node][96] layout; lane gather stays 3 independent loads)
    for (int i = tid; i < 64 * 32; i += 256) {
        int nl = i >> 5, j0 = i & 31;
        int node = nb + nl;
        if (node < n) {
            const float* orow = Os + nl * 100;
            __half* fo = g_fth + (size_t)node * 96;
            fo[j0]      = __float2half(orow[j0]);
            fo[j0 + 32] = __float2half(orow[j0 + 32]);
            fo[j0 + 64] = __float2half(orow[j0 + 64]);
        }
    }
    // el/er: 64 threads, one node each
    if (tid < 64 && nb + tid < n) {
        const float4* orow = (const float4*)(Os + tid * 100);
        float el[3] = {0.f, 0.f, 0.f}, er[3] = {0.f, 0.f, 0.f};
        #pragma unroll
        for (int q = 0; q < 24; q++) {
            float4 v = orow[q];
            float xs[4] = {v.x, v.y, v.z, v.w};
            #pragma unroll
            for (int j = 0; j < 4; j++) {
                int cix = q * 4 + j, h = cix >> 5;
                el[h] = fmaf(xs[j], sal[cix], el[h]);
                er[h] = fmaf(xs[j], sar[cix], er[h]);
            }
        }
        g_el4[nb + tid] = make_float4(el[0], el[1], el[2], 0.f);
        g_er4[nb + tid] = make_float4(er[0], er[1], er[2], 0.f);
    }
}

// ---------------- eepre: efeats GEMV only (edge order; needs only Ve) --------------
__global__ void k_eepre(const float* __restrict__ ef, int e_cnt) {
    __shared__ float sVe[192];
    if (threadIdx.x < 192) sVe[threadIdx.x] = ((const float*)g_Ve)[threadIdx.x];
    __syncthreads();
    int e = blockIdx.x * blockDim.x + threadIdx.x;
    if (e >= e_cnt) return;
    const float4* p = (const float4*)(ef + (size_t)e * 32);
    float acc0 = 0, acc1 = 0, acc2 = 0, acc3 = 0, acc4 = 0, acc5 = 0;
    #pragma unroll
    for (int q = 0; q < 8; q++) {
        float4 v = p[q];
        float xs[4] = {v.x, v.y, v.z, v.w};
        #pragma unroll
        for (int j = 0; j < 4; j++) {
            int d = q * 4 + j;
            float x = xs[j];
            acc0 = fmaf(x, sVe[d * 3 + 0],      acc0);
            acc1 = fmaf(x, sVe[d * 3 + 1],      acc1);
            acc2 = fmaf(x, sVe[d * 3 + 2],      acc2);
            acc3 = fmaf(x, sVe[96 + d * 3 + 0], acc3);
            acc4 = fmaf(x, sVe[96 + d * 3 + 1], acc4);
            acc5 = fmaf(x, sVe[96 + d * 3 + 2], acc5);
        }
    }
    g_eepA[e] = make_float4(acc0, acc1, acc2, 0.f);
    g_eepB[e] = make_float4(acc3, acc4, acc5, 0.f);
}

// ---------------- combine: el/er gather + exp, scatter to CSR ----------------------
__global__ void k_combine(const int* __restrict__ src, const int* __restrict__ dst,
                          int e_cnt) {
    int e = blockIdx.x * blockDim.x + threadIdx.x;
    if (e >= e_cnt) return;
    float4 A = g_eepA[e];
    int sn = src[e], dn = dst[e];
    float4 el = g_el4[sn];
    float4 er = g_er4[dn];
    float x0 = __expf(leaky(el.x + er.x + A.x));
    float x1 = __expf(leaky(el.y + er.y + A.y));
    float x2 = __expf(leaky(el.z + er.z + A.z));
    int pp = g_pos[e];
    g_wc4[pp]   = make_float4(x0, x1, x2, 0.f);
    g_eec24[pp] = g_eepB[e];
}

// ---------------- layer-2 exp weights: edge-parallel over CSR slots ----------------
__global__ void k_wc2(int e_cnt) {
    int i = blockIdx.x * blockDim.x + threadIdx.x;
    if (i >= e_cnt) return;
    int sn = g_srcc[i], dn = g_dstc[i];
    float4 el = g_el4[sn];
    float4 er = g_er4[dn];
    float4 ee = g_eec24[i];
    float x0 = __expf(leaky(el.x + er.x + ee.x));
    float x1 = __expf(leaky(el.y + er.y + ee.y));
    float x2 = __expf(leaky(el.z + er.z + ee.z));
    g_wc4[i] = make_float4(x0, x1, x2, 0.f);
}

// ---------------- CSR build ----------------
__global__ void k_zero_deg(int n) {
    int i = blockIdx.x * blockDim.x + threadIdx.x;
    if (i < n) g_deg[i] = 0;
}
__global__ void k_deg(const int* __restrict__ dst, int e) {
    int i = blockIdx.x * blockDim.x + threadIdx.x;
    if (i < e) atomicAdd(&g_deg[dst[i]], 1);
}
__global__ void k_scan1(int n) {
    __shared__ int s[1024];
    int idx = blockIdx.x * 1024 + threadIdx.x;
    int v = (idx < n) ? g_deg[idx] : 0;
    s[threadIdx.x] = v;
    __syncthreads();
    #pragma unroll
    for (int off = 1; off < 1024; off <<= 1) {
        int t = (threadIdx.x >= off) ? s[threadIdx.x - off] : 0;
        __syncthreads();
        s[threadIdx.x] += t;
        __syncthreads();
    }
    if (idx < n) g_off[idx] = s[threadIdx.x] - v;
    if (threadIdx.x == 1023) g_bsum[blockIdx.x] = s[1023];
}
__global__ void k_scan2(int nb) {
    __shared__ int s[128];
    int tid = threadIdx.x;
    int v = (tid < nb) ? g_bsum[tid] : 0;
    s[tid] = v;
    __syncthreads();
    #pragma unroll
    for (int off = 1; off < 128; off <<= 1) {
        int t = (tid >= off) ? s[tid - off] : 0;
        __syncthreads();
        s[tid] += t;
        __syncthreads();
    }
    if (tid < nb) g_boff[tid] = s[tid] - v;
}
__global__ void k_scan3(int n, int e) {
    int idx = blockIdx.x * 1024 + threadIdx.x;
    if (idx < n) {
        int o = g_off[idx] + g_boff[blockIdx.x];
        g_off[idx] = o;
        g_woff[idx] = o;
    }
    if (idx == 0) g_off[n] = e;
}
__global__ void k_scatter(const int* __restrict__ src, const int* __restrict__ dst, int e) {
    int i = blockIdx.x * blockDim.x + threadIdx.x;
    if (i < e) {
        int d = dst[i];
        int p = atomicAdd(&g_woff[d], 1);
        g_srcc[p] = src[i];
        g_dstc[p] = d;
        g_pos[i] = p;
    }
}

// ---------------- conv: single sweep; fp16 gathers (3 independent LDG.U16/edge) ----
__global__ void __launch_bounds__(64)
k_conv(const float* __restrict__ bias, int n, int do_relu) {
    int gw   = (blockIdx.x * blockDim.x + threadIdx.x) >> 5;
    int lane = threadIdx.x & 31;
    if (gw >= n) return;
    int beg = g_off[gw], end = g_off[gw + 1];
    float b0 = bias[lane], b1 = bias[lane + 32], b2 = bias[lane + 64];
    float out0, out1, out2;
    if (beg == end) {
        out0 = b0; out1 = b1; out2 = b2;
    } else {
        float s0 = 0.f, s1 = 0.f, s2 = 0.f;
        float a0 = 0.f, a1 = 0.f, a2 = 0.f;
        #pragma unroll 8
        for (int i = beg; i < end; i++) {
            float4 x = g_wc4[i];
            int sn = g_srcc[i];
            const __half* fr = g_fth + (size_t)sn * 96;
            __half h0 = fr[lane];
            __half h1 = fr[lane + 32];
            __half h2 = fr[lane + 64];
            a0 = fmaf(x.x, __half2float(h0), a0);
            a1 = fmaf(x.y, __half2float(h1), a1);
            a2 = fmaf(x.z, __half2float(h2), a2);
            s0 += x.x; s1 += x.y; s2 += x.z;
        }
        out0 = a0 / s0 + b0;
        out1 = a1 / s1 + b1;
        out2 = a2 / s2 + b2;
    }
    if (do_relu) {
        out0 = fmaxf(out0, 0.f); out1 = fmaxf(out1, 0.f); out2 = fmaxf(out2, 0.f);
    }
    float* o = g_h + (size_t)gw * 96;
    o[lane] = out0; o[lane + 32] = out1; o[lane + 64] = out2;
}

// ---------------- per-node P = h@Wp_top, Q = h@Wp_bot + bp (float4 reads) ----------
__global__ void k_pq(const float* __restrict__ Wp, const float* __restrict__ bp, int n) {
    __shared__ float sW[1920];
    __shared__ float sb[10];
    for (int i = threadIdx.x; i < 1920; i += blockDim.x) sW[i] = Wp[i];
    if (threadIdx.x < 10) sb[threadIdx.x] = bp[threadIdx.x];
    __syncthreads();
    int t = blockIdx.x * blockDim.x + threadIdx.x;
    if (t >= n * 10) return;
    int node = t / 10, c = t % 10;
    const float4* hr = (const float4*)(g_h + (size_t)node * 96);
    float p = 0.f, q = 0.f;
    #pragma unroll 6
    for (int jq = 0; jq < 24; jq++) {
        float4 v = hr[jq];
        float xs[4] = {v.x, v.y, v.z, v.w};
        #pragma unroll
        for (int u = 0; u < 4; u++) {
            int j = jq * 4 + u;
            p = fmaf(xs[u], sW[j * 10 + c], p);
            q = fmaf(xs[u], sW[(96 + j) * 10 + c], q);
        }
    }
    g_P[node * 12 + c] = p;
    g_Q[node * 12 + c] = q + sb[c];
}

// ---------------- score[e,:] = P[src] + Q[dst]; float4 gathers + float4 stores -----
__global__ void k_score(const int* __restrict__ src, const int* __restrict__ dst,
                        float* __restrict__ out, int e) {
    __shared__ float sm[2560];
    int tid = threadIdx.x;
    int eb = blockIdx.x * 256;
    int ed = eb + tid;
    if (ed < e) {
        int sn = src[ed], dn = dst[ed];
        const float4* P4 = (const float4*)(g_P + sn * 12);
        const float4* Q4 = (const float4*)(g_Q + dn * 12);
        float4 p0 = P4[0], p1 = P4[1], p2 = P4[2];
        float4 q0 = Q4[0], q1 = Q4[1], q2 = Q4[2];
        float* s = sm + tid * 10;
        s[0] = p0.x + q0.x; s[1] = p0.y + q0.y; s[2] = p0.z + q0.z; s[3] = p0.w + q0.w;
        s[4] = p1.x + q1.x; s[5] = p1.y + q1.y; s[6] = p1.z + q1.z; s[7] = p1.w + q1.w;
        s[8] = p2.x + q2.x; s[9] = p2.y + q2.y;
    }
    __syncthreads();
    int rem = e - eb;
    if (rem >= 256) {
        float4* o4 = (float4*)(out + (size_t)eb * 10);
        const float4* s4 = (const float4*)sm;
        for (int i = tid; i < 640; i += 256) o4[i] = s4[i];
    } else {
        int cnt = rem * 10;
        for (int i = tid; i < cnt; i += 256)
            out[(size_t)eb * 10 + i] = sm[i];
    }
}

// ---------------- driver: three-stream DAG ----------------
extern "C" void kernel_launch(void* const* d_in, const int* in_sizes, int n_in,
                              void* d_out, int out_size) {
    const float* nfeats = (const float*)d_in[0];
    const float* efeats = (const float*)d_in[1];
    const int*   src    = (const int*)  d_in[2];
    const int*   dst    = (const int*)  d_in[3];
    const float* W1  = (const float*)d_in[4];
    const float* We1 = (const float*)d_in[5];
    const float* al1 = (const float*)d_in[6];
    const float* ar1 = (const float*)d_in[7];
    const float* ae1 = (const float*)d_in[8];
    const float* b1  = (const float*)d_in[9];
    const float* W2  = (const float*)d_in[10];
    const float* We2 = (const float*)d_in[11];
    const float* al2 = (const float*)d_in[12];
    const float* ar2 = (const float*)d_in[13];
    const float* ae2 = (const float*)d_in[14];
    const float* b2  = (const float*)d_in[15];
    const float* Wp  = (const float*)d_in[16];
    const float* bp  = (const float*)d_in[17];
    float* out = (float*)d_out;

    int n = in_sizes[0] / 64;   // 100000
    int e = in_sizes[2];        // 1600000

    int eb   = (e + 255) / 256;
    int nb   = (n + 255) / 256;
    int ncb  = (n + 1) / 2;          // conv: 64-thr blocks, 2 nodes each
    int ngb  = (n + 63) / 64;
    int nb1k = (n + 1023) / 1024;

    static cudaStream_t s1 = nullptr, s2 = nullptr;
    static cudaEvent_t evFork = nullptr, evVe = nullptr, evCsr = nullptr, evEe = nullptr;
    if (s1 == nullptr) {
        cudaStreamCreateWithFlags(&s1, cudaStreamNonBlocking);
        cudaStreamCreateWithFlags(&s2, cudaStreamNonBlocking);
        cudaEventCreateWithFlags(&evFork, cudaEventDisableTiming);
        cudaEventCreateWithFlags(&evVe,   cudaEventDisableTiming);
        cudaEventCreateWithFlags(&evCsr,  cudaEventDisableTiming);
        cudaEventCreateWithFlags(&evEe,   cudaEventDisableTiming);
    }

    // fork
    cudaEventRecord(evFork, 0);
    cudaStreamWaitEvent(s1, evFork, 0);

    // s1: CSR build
    k_zero_deg<<<nb, 256, 0, s1>>>(n);
    k_deg<<<eb, 256, 0, s1>>>(dst, e);
    k_scan1<<<nb1k, 1024, 0, s1>>>(n);
    k_scan2<<<1, 128, 0, s1>>>(nb1k);
    k_scan3<<<nb1k, 1024, 0, s1>>>(n, e);
    k_scatter<<<eb, 256, 0, s1>>>(src, dst, e);
    cudaEventRecord(evCsr, s1);

    // main: ve -> (s2: eepre) || wgemm64
    k_ve<<<1, 192>>>(We1, ae1, We2, ae2);
    cudaEventRecord(evVe, 0);
    cudaStreamWaitEvent(s2, evVe, 0);
    k_eepre<<<eb, 256, 0, s2>>>(efeats, e);
    cudaEventRecord(evEe, s2);

    k_wgemm<64><<<ngb, 256>>>(nfeats, W1, al1, ar1, n);

    // join
    cudaStreamWaitEvent(0, evCsr, 0);
    cudaStreamWaitEvent(0, evEe, 0);

    // layer 1
    k_combine<<<eb, 256>>>(src, dst, e);
    k_conv<<<ncb, 64>>>(b1, n, 1);

    // layer 2
    k_wgemm<96><<<ngb, 256>>>(nullptr, W2, al2, ar2, n);
    k_wc2<<<eb, 256>>>(e);
    k_conv<<<ncb, 64>>>(b2, n, 0);

    // edge score head
    k_pq<<<(n * 10 + 255) / 256, 256>>>(Wp, bp, n);
    k_score<<<eb, 256>>>(src, dst, out, e);
}